// round 14
// baseline (speedup 1.0000x reference)
#include <cuda_runtime.h>
#include <cuda_bf16.h>
#include <stdint.h>

#define NUM_ROWS 16384
#define HDIM     2048
#define KSEL     4
#define NEXP     64
#define NTOT     (NUM_ROWS * KSEL)   /* 65536 expanded slots */
#define NCHUNK   256
#define CHUNK    (NTOT / NCHUNK)     /* 256 items per chunk */
#define NWARP    (CHUNK / 32)        /* 8 warps per chunk block */

/* output layout (floats) */
#define X_OFF   0
#define RI_OFF  ((size_t)NTOT * HDIM)                 /* 134217728 */
#define CNT_OFF (RI_OFF + NTOT)                        /* +65536 */
#define SC_OFF  (CNT_OFF + NEXP)                       /* +64 */

/* scratch (no cudaMalloc allowed).
 * g_counts is TRANSPOSED: [expert][chunk] so the scan walks contiguously. */
__device__ int g_counts[NEXP * NCHUNK];   /* counts -> stable bases */
__device__ int g_rank[NTOT];              /* intra-chunk stable rank */
__device__ unsigned g_ticket = 0;         /* monotonic across replays */

/* ---- K1: histogram + stable rank; LAST-arriving block also scans ---- */
__global__ void __launch_bounds__(CHUNK) k_setup(const int* __restrict__ eidx,
                                                 float* __restrict__ out) {
    __shared__ int shcnt[NWARP][NEXP];
    __shared__ int offs[NEXP];
    __shared__ int s_last;

    int t = threadIdx.x;
    int c = blockIdx.x;
    int w = t >> 5, lane = t & 31;

    for (int j = t; j < NWARP * NEXP; j += CHUNK)
        ((int*)shcnt)[j] = 0;
    __syncthreads();

    int i = c * CHUNK + t;
    int e = eidx[i];
    unsigned m = __match_any_sync(0xffffffffu, e);
    int rank = __popc(m & ((1u << lane) - 1));
    if (rank == 0) shcnt[w][e] = __popc(m);
    __syncthreads();

    int off = 0;
#pragma unroll
    for (int w2 = 0; w2 < NWARP; ++w2)
        if (w2 < w) off += shcnt[w2][e];
    g_rank[i] = off + rank;

    if (t < NEXP) {
        int s = 0;
#pragma unroll
        for (int w2 = 0; w2 < NWARP; ++w2) s += shcnt[w2][t];
        g_counts[t * NCHUNK + c] = s;     /* transposed store */
    }
    __threadfence();
    __syncthreads();

#if __CUDA_ARCH__ >= 900
    cudaTriggerProgrammaticLaunchCompletion();
#endif

    if (t == 0) {
        unsigned ticket = atomicAdd(&g_ticket, 1u);
        s_last = ((ticket % NCHUNK) == NCHUNK - 1);
    }
    __syncthreads();
    if (!s_last) return;

    /* ---- last block: scan. expert e2 = t>>2, group g2 = t&3 owns 64
     * CONTIGUOUS chunks -> 16 int4 loads, register-cached. ---- */
    __threadfence();
    int e2 = t >> 2;
    int g2 = t & 3;

    int4 v4[16];
    int partial = 0;
    const int4* __restrict__ p = (const int4*)(g_counts + e2 * NCHUNK + g2 * 64);
#pragma unroll
    for (int j = 0; j < 16; ++j) {
        v4[j] = p[j];
        partial += v4[j].x + v4[j].y + v4[j].z + v4[j].w;
    }

    int inc = partial;
#pragma unroll
    for (int d = 1; d < 4; d <<= 1) {
        int y = __shfl_up_sync(0xffffffffu, inc, d, 4);
        if (g2 >= d) inc += y;
    }
    if (g2 == 3) shcnt[0][e2] = inc;   /* expert totals */
    __syncthreads();
    if (t == 0) {
        int run = 0;
        for (int j = 0; j < NEXP; ++j) { offs[j] = run; run += shcnt[0][j]; }
    }
    __syncthreads();
    if (t < NEXP) out[CNT_OFF + t] = (float)shcnt[0][t];

    int run = offs[e2] + (inc - partial);   /* exclusive base for this group */
    int4* __restrict__ q = (int4*)(g_counts + e2 * NCHUNK + g2 * 64);
#pragma unroll
    for (int j = 0; j < 16; ++j) {
        int4 b;
        b.x = run; run += v4[j].x;
        b.y = run; run += v4[j].y;
        b.z = run; run += v4[j].z;
        b.w = run; run += v4[j].w;
        q[j] = b;
    }
}

/* ---- K2: big gather copy + final dest resolve + small outputs ----
 * PROVEN shape: 128 threads, 1 row per block, interleaved load->store.
 * v0 prefetched before the grid-dependency sync (src independent of setup). */
__global__ void __launch_bounds__(128) k_copy(const float* __restrict__ x,
                                              const int* __restrict__ eidx,
                                              const float* __restrict__ scale,
                                              float* __restrict__ out) {
    int i = blockIdx.x;          /* expanded slot 0..NTOT-1 */
    int src = i >> 2;
    int t = threadIdx.x;
    const float4* __restrict__ s = (const float4*)(x + (size_t)src * HDIM);
    float4 v0 = s[t];

#if __CUDA_ARCH__ >= 900
    cudaGridDependencySynchronize();
#endif

    int e = __ldg(eidx + i);
    int d = g_counts[e * NCHUNK + (i >> 8)] + g_rank[i];

    float4* __restrict__ o = (float4*)(out + X_OFF + (size_t)d * HDIM);
    o[t] = v0;
#pragma unroll
    for (int j = 1; j < 4; ++j) {
        int idx = t + j * 128;   /* 512 float4 per row */
        o[idx] = s[idx];
    }
    if (t == 0) {
        out[RI_OFF + i] = (float)d;
        out[SC_OFF + d] = scale[src];
    }
}

extern "C" void kernel_launch(void* const* d_in, const int* in_sizes, int n_in,
                              void* d_out, int out_size) {
    const float* x     = (const float*)d_in[0];
    const int*   eidx  = (const int*)d_in[1];
    const float* scale = (const float*)d_in[2];
    float* out = (float*)d_out;

    k_setup<<<NCHUNK, CHUNK>>>(eidx, out);

    cudaLaunchAttribute attr[1];
    attr[0].id = cudaLaunchAttributeProgrammaticStreamSerialization;
    attr[0].val.programmaticStreamSerializationAllowed = 1;

    cudaLaunchConfig_t cfg = {};
    cfg.gridDim  = dim3(NTOT, 1, 1);
    cfg.blockDim = dim3(128, 1, 1);
    cfg.dynamicSmemBytes = 0;
    cfg.stream = 0;
    cfg.attrs = attr;
    cfg.numAttrs = 1;
    cudaLaunchKernelEx(&cfg, k_copy, x, eidx, scale, out);
}

// round 15
// speedup vs baseline: 1.0159x; 1.0159x over previous
#include <cuda_runtime.h>
#include <cuda_bf16.h>
#include <stdint.h>

#define NUM_ROWS 16384
#define HDIM     2048
#define KSEL     4
#define NEXP     64
#define NTOT     (NUM_ROWS * KSEL)   /* 65536 expanded slots */
#define NCHUNK   256
#define CHUNK    (NTOT / NCHUNK)     /* 256 items per chunk */
#define NWARP    (CHUNK / 32)        /* 8 warps per chunk block */

/* output layout (floats) */
#define X_OFF   0
#define RI_OFF  ((size_t)NTOT * HDIM)                 /* 134217728 */
#define CNT_OFF (RI_OFF + NTOT)                        /* +65536 */
#define SC_OFF  (CNT_OFF + NEXP)                       /* +64 */

/* scratch (no cudaMalloc allowed).
 * g_counts is TRANSPOSED: [expert][chunk] so the scan walks contiguously. */
__device__ int g_counts[NEXP * NCHUNK];   /* counts -> stable bases */
__device__ int g_rank[NTOT];              /* intra-chunk stable rank */
__device__ unsigned g_ticket = 0;         /* monotonic across replays */

/* ---- K1: histogram + stable rank; LAST-arriving block also scans ---- */
__global__ void __launch_bounds__(CHUNK) k_setup(const int* __restrict__ eidx,
                                                 float* __restrict__ out) {
    __shared__ int shcnt[NWARP][NEXP];
    __shared__ int offs[NEXP];
    __shared__ int s_last;

    int t = threadIdx.x;
    int c = blockIdx.x;
    int w = t >> 5, lane = t & 31;

    for (int j = t; j < NWARP * NEXP; j += CHUNK)
        ((int*)shcnt)[j] = 0;
    __syncthreads();

    int i = c * CHUNK + t;
    int e = eidx[i];
    unsigned m = __match_any_sync(0xffffffffu, e);
    int rank = __popc(m & ((1u << lane) - 1));
    if (rank == 0) shcnt[w][e] = __popc(m);
    __syncthreads();

    int off = 0;
#pragma unroll
    for (int w2 = 0; w2 < NWARP; ++w2)
        if (w2 < w) off += shcnt[w2][e];
    g_rank[i] = off + rank;

    if (t < NEXP) {
        int s = 0;
#pragma unroll
        for (int w2 = 0; w2 < NWARP; ++w2) s += shcnt[w2][t];
        g_counts[t * NCHUNK + c] = s;     /* transposed store */
    }
    __threadfence();
    __syncthreads();

#if __CUDA_ARCH__ >= 900
    cudaTriggerProgrammaticLaunchCompletion();
#endif

    if (t == 0) {
        unsigned ticket = atomicAdd(&g_ticket, 1u);
        s_last = ((ticket % NCHUNK) == NCHUNK - 1);
    }
    __syncthreads();
    if (!s_last) return;

    /* ---- last block: scan. expert e2 = t>>2, group g2 = t&3 owns 64
     * CONTIGUOUS chunks -> 16 int4 loads, register-cached rewrite. ---- */
    __threadfence();
    int e2 = t >> 2;
    int g2 = t & 3;

    int4 v4[16];
    int partial = 0;
    const int4* __restrict__ p = (const int4*)(g_counts + e2 * NCHUNK + g2 * 64);
#pragma unroll
    for (int j = 0; j < 16; ++j) {
        v4[j] = p[j];
        partial += v4[j].x + v4[j].y + v4[j].z + v4[j].w;
    }

    int inc = partial;
#pragma unroll
    for (int d = 1; d < 4; d <<= 1) {
        int y = __shfl_up_sync(0xffffffffu, inc, d, 4);
        if (g2 >= d) inc += y;
    }
    if (g2 == 3) shcnt[0][e2] = inc;   /* expert totals */
    __syncthreads();
    if (t == 0) {
        int run = 0;
        for (int j = 0; j < NEXP; ++j) { offs[j] = run; run += shcnt[0][j]; }
    }
    __syncthreads();
    if (t < NEXP) out[CNT_OFF + t] = (float)shcnt[0][t];

    int run = offs[e2] + (inc - partial);   /* exclusive base for this group */
    int4* __restrict__ q = (int4*)(g_counts + e2 * NCHUNK + g2 * 64);
#pragma unroll
    for (int j = 0; j < 16; ++j) {
        int4 b;
        b.x = run; run += v4[j].x;
        b.y = run; run += v4[j].y;
        b.z = run; run += v4[j].z;
        b.w = run; run += v4[j].w;
        q[j] = b;
    }
}

/* ---- K2: big gather copy + final dest resolve + small outputs ----
 * PROVEN shape (R13): sync at entry, resolve, then 128 threads x
 * interleaved 4x load->store. NO pre-sync prefetch. */
__global__ void __launch_bounds__(128) k_copy(const float* __restrict__ x,
                                              const int* __restrict__ eidx,
                                              const float* __restrict__ scale,
                                              float* __restrict__ out) {
#if __CUDA_ARCH__ >= 900
    cudaGridDependencySynchronize();
#endif
    int i = blockIdx.x;          /* expanded slot 0..NTOT-1 */
    int e = __ldg(eidx + i);
    int d = g_counts[e * NCHUNK + (i >> 8)] + g_rank[i];
    int src = i >> 2;

    const float4* __restrict__ s = (const float4*)(x + (size_t)src * HDIM);
    float4* __restrict__ o = (float4*)(out + X_OFF + (size_t)d * HDIM);
#pragma unroll
    for (int j = 0; j < 4; ++j) {
        int idx = threadIdx.x + j * 128;   /* 512 float4 per row */
        o[idx] = s[idx];
    }
    if (threadIdx.x == 0) {
        out[RI_OFF + i] = (float)d;
        out[SC_OFF + d] = scale[src];
    }
}

extern "C" void kernel_launch(void* const* d_in, const int* in_sizes, int n_in,
                              void* d_out, int out_size) {
    const float* x     = (const float*)d_in[0];
    const int*   eidx  = (const int*)d_in[1];
    const float* scale = (const float*)d_in[2];
    float* out = (float*)d_out;

    k_setup<<<NCHUNK, CHUNK>>>(eidx, out);

    cudaLaunchAttribute attr[1];
    attr[0].id = cudaLaunchAttributeProgrammaticStreamSerialization;
    attr[0].val.programmaticStreamSerializationAllowed = 1;

    cudaLaunchConfig_t cfg = {};
    cfg.gridDim  = dim3(NTOT, 1, 1);
    cfg.blockDim = dim3(128, 1, 1);
    cfg.dynamicSmemBytes = 0;
    cfg.stream = 0;
    cfg.attrs = attr;
    cfg.numAttrs = 1;
    cudaLaunchKernelEx(&cfg, k_copy, x, eidx, scale, out);
}